// round 15
// baseline (speedup 1.0000x reference)
#include <cuda_runtime.h>
#include <cuda_bf16.h>
#include <math.h>
#include <stdint.h>

#define MAXN 100000
#define MAXE 3200000

// ---------------- scratch (static device globals; no allocation) -------------
__device__ __nv_bfloat16 g_hs1[(size_t)MAXN * 128]; // (X@W1)*dinv, bf16 payload
__device__ float g_h1 [(size_t)MAXN * 128];         // h1
__device__ __nv_bfloat16 g_h2s[(size_t)MAXN * 64];  // (h1@W2)*dinv, bf16 payload
__device__ float g_h2 [(size_t)MAXN * 64];          // h2
__device__ float g_s  [(size_t)MAXN * 8];           // exp(attention logits)
__device__ float g_dinv[MAXN];
__device__ int   g_cnt [MAXN];
__device__ int   g_tmp [MAXN];
__device__ int   g_off [MAXN + 1];
__device__ int   g_cur [MAXN];
__device__ int   g_ecsr[MAXE];
__device__ int   g_bsum[128];
__device__ float g_Z[8];
__device__ float g_G[512];
__device__ float g_C[64];

// ---------------- cp.async helpers --------------------------------------------
__device__ __forceinline__ void cp_async16(void* smem_dst, const void* gsrc) {
    uint32_t d = (uint32_t)__cvta_generic_to_shared(smem_dst);
    asm volatile("cp.async.cg.shared.global [%0], [%1], 16;" :: "r"(d), "l"(gsrc));
}
#define CP_COMMIT() asm volatile("cp.async.commit_group;" ::: "memory")
#define CP_WAIT(N)  asm volatile("cp.async.wait_group %0;" :: "n"(N) : "memory")

// ---------------- bf16 unpack helpers (pure ALU, no cvt pipe) -----------------
__device__ __forceinline__ float bf_lo(unsigned p) { return __uint_as_float(p << 16); }
__device__ __forceinline__ float bf_hi(unsigned p) { return __uint_as_float(p & 0xFFFF0000u); }

// ---------------- init / degree / CSR build ----------------------------------
__global__ void k_init(int n) {
    int i = blockIdx.x * blockDim.x + threadIdx.x;
    if (i < n)   g_cnt[i] = 0;
    if (i < 512) g_G[i] = 0.0f;
    if (i < 64)  g_C[i] = 0.0f;
    if (i < 8)   g_Z[i] = 0.0f;
}

__global__ void k_deg(const int* __restrict__ dst, int e) {
    int i = blockIdx.x * blockDim.x + threadIdx.x;
    if (i < e) atomicAdd(&g_cnt[dst[i]], 1);
}

__global__ void k_scan1(int n) {
    __shared__ int sh[1024];
    int i = blockIdx.x * 1024 + threadIdx.x;
    int v = (i < n) ? g_cnt[i] : 0;
    if (i < n) g_dinv[i] = rsqrtf((float)(v + 1)); // +1 self loop
    sh[threadIdx.x] = v;
    __syncthreads();
#pragma unroll
    for (int off = 1; off < 1024; off <<= 1) {
        int t = (threadIdx.x >= off) ? sh[threadIdx.x - off] : 0;
        __syncthreads();
        sh[threadIdx.x] += t;
        __syncthreads();
    }
    if (i < n) g_tmp[i] = sh[threadIdx.x];
    if (threadIdx.x == 1023) g_bsum[blockIdx.x] = sh[1023];
}

// scan3 with fused block-prefix reduction over g_bsum (R12-proven)
__global__ void k_scan3(int n) {
    __shared__ int red[4];
    __shared__ int pre;
    int t = threadIdx.x;
    int v = (t < blockIdx.x) ? g_bsum[t] : 0;
#pragma unroll
    for (int off = 16; off > 0; off >>= 1) v += __shfl_down_sync(0xFFFFFFFF, v, off);
    if (t < 128 && (t & 31) == 0) red[t >> 5] = v;
    __syncthreads();
    if (t == 0) pre = red[0] + red[1] + red[2] + red[3];
    __syncthreads();
    int i = blockIdx.x * 1024 + t;
    if (i < n) {
        int inc = g_tmp[i] + pre;
        g_off[i + 1] = inc;
        g_cur[i]     = inc - g_cnt[i];
    }
    if (i == 0) g_off[0] = 0;
}

__global__ void k_bucket(const int* __restrict__ src, const int* __restrict__ dst, int e) {
    int i = blockIdx.x * blockDim.x + threadIdx.x;
    if (i < e) {
        int d   = dst[i];
        int pos = atomicAdd(&g_cur[d], 1);
        g_ecsr[pos] = src[i];
    }
}

// ---------------- cp.async double-buffered 4x4 GEMM ---------------------------
// out_bf16 = (A@W)*dinv[row]
template <int K, int C>
__global__ void __launch_bounds__(256, 2)
gemm_kernel(const float* __restrict__ A, const float* __restrict__ W,
            __nv_bfloat16* __restrict__ outb, int n) {
    constexpr int BM  = 128, TN = 4;
    constexpr int NCG = C / TN;
    constexpr int NRG = 256 / NCG;
    constexpr int TM  = BM / NRG;
    constexpr int KC  = 32;
    constexpr int NCH = K / KC;
    constexpr int ASZ = BM * KC;   // floats
    constexpr int BSZ = KC * C;

    extern __shared__ float sm[];
    float* AshB[2] = { sm, sm + ASZ };
    float* BshB[2] = { sm + 2 * ASZ, sm + 2 * ASZ + BSZ };

    int tid = threadIdx.x;
    int m0  = blockIdx.x * BM;
    int tc  = tid % NCG;
    int tr  = tid / NCG;

    auto load = [&](int ch, int b) {
        int kc = ch * KC;
        float* Ad = AshB[b];
        float* Bd = BshB[b];
#pragma unroll
        for (int t = tid; t < ASZ / 4; t += 256) {
            int r  = t / (KC / 4);
            int c4 = t % (KC / 4);
            int row = m0 + r;
            if (row >= n) row = n - 1;  // clamp; garbage rows masked at store
            cp_async16(&Ad[r * KC + c4 * 4], &A[(size_t)row * K + kc + c4 * 4]);
        }
#pragma unroll
        for (int t = tid; t < BSZ / 4; t += 256) {
            int r  = t / (C / 4);
            int c4 = t % (C / 4);
            cp_async16(&Bd[r * C + c4 * 4], &W[(size_t)(kc + r) * C + c4 * 4]);
        }
        CP_COMMIT();
    };

    float acc[TM][TN];
#pragma unroll
    for (int i = 0; i < TM; i++)
#pragma unroll
        for (int j = 0; j < TN; j++) acc[i][j] = 0.0f;

    load(0, 0);
    for (int ch = 0; ch < NCH; ch++) {
        if (ch + 1 < NCH) { load(ch + 1, (ch + 1) & 1); CP_WAIT(1); }
        else              { CP_WAIT(0); }
        __syncthreads();
        const float* Acur = AshB[ch & 1];
        const float* Bcur = BshB[ch & 1];
#pragma unroll
        for (int k4 = 0; k4 < KC / 4; k4++) {
            float4 b0 = *reinterpret_cast<const float4*>(&Bcur[(k4 * 4 + 0) * C + tc * TN]);
            float4 b1 = *reinterpret_cast<const float4*>(&Bcur[(k4 * 4 + 1) * C + tc * TN]);
            float4 b2 = *reinterpret_cast<const float4*>(&Bcur[(k4 * 4 + 2) * C + tc * TN]);
            float4 b3 = *reinterpret_cast<const float4*>(&Bcur[(k4 * 4 + 3) * C + tc * TN]);
#pragma unroll
            for (int i = 0; i < TM; i++) {
                float4 a = *reinterpret_cast<const float4*>(&Acur[(tr * TM + i) * KC + k4 * 4]);
                acc[i][0] += a.x * b0.x + a.y * b1.x + a.z * b2.x + a.w * b3.x;
                acc[i][1] += a.x * b0.y + a.y * b1.y + a.z * b2.y + a.w * b3.y;
                acc[i][2] += a.x * b0.z + a.y * b1.z + a.z * b2.z + a.w * b3.z;
                acc[i][3] += a.x * b0.w + a.y * b1.w + a.z * b2.w + a.w * b3.w;
            }
        }
        __syncthreads();
    }

#pragma unroll
    for (int i = 0; i < TM; i++) {
        int row = m0 + tr * TM + i;
        if (row >= n) continue;
        float sc = g_dinv[row];
        __nv_bfloat162 lo = __floats2bfloat162_rn(acc[i][0] * sc, acc[i][1] * sc);
        __nv_bfloat162 hi = __floats2bfloat162_rn(acc[i][2] * sc, acc[i][3] * sc);
        uint2 pk = make_uint2(*reinterpret_cast<unsigned*>(&lo),
                              *reinterpret_cast<unsigned*>(&hi));
        *reinterpret_cast<uint2*>(&outb[(size_t)row * C + tc * TN]) = pk;
    }
}

// ---------------- gemm3 fused with attention logits (cp.async pipeline) -------
// a1 = tanh(h2@Wf1 + bf1) kept in smem; s = a1@Wf2 + bf2; g_s = exp(s);
// Z partials block-reduced, 8 global atomics per block.
__global__ void __launch_bounds__(256, 2)
gemm3_logits(const float* __restrict__ A,      // h2 [n,64]
             const float* __restrict__ Wf1,    // [64,64]
             const float* __restrict__ bf1,    // [64]
             const float* __restrict__ Wf2,    // [64,8]
             const float* __restrict__ bf2,    // [8]
             int n) {
    constexpr int K = 64, C = 64;
    constexpr int BM = 128, TN = 4;
    constexpr int NCG = C / TN;   // 16
    constexpr int TM  = 8;
    constexpr int KC  = 32;
    constexpr int NCH = K / KC;   // 2
    constexpr int ASZ = BM * KC;  // 4096 floats
    constexpr int BSZ = KC * C;   // 2048 floats

    extern __shared__ float sm[]; // 12288 floats; a1sh (8320) aliases front
    float* AshB[2] = { sm, sm + ASZ };
    float* BshB[2] = { sm + 2 * ASZ, sm + 2 * ASZ + BSZ };
    float* a1sh    = sm;          // [BM][65] padded, reused after compute

    __shared__ float Wf2sh[64 * 8];
    __shared__ float bf2sh[8];
    __shared__ float redZ[8];

    int tid = threadIdx.x;
    int m0  = blockIdx.x * BM;
    int tc  = tid % NCG;
    int tr  = tid / NCG;

    for (int t = tid; t < 512; t += 256) Wf2sh[t] = Wf2[t];
    if (tid < 8) { bf2sh[tid] = bf2[tid]; redZ[tid] = 0.0f; }

    auto load = [&](int ch, int b) {
        int kc = ch * KC;
        float* Ad = AshB[b];
        float* Bd = BshB[b];
#pragma unroll
        for (int t = tid; t < ASZ / 4; t += 256) {
            int r  = t / (KC / 4);
            int c4 = t % (KC / 4);
            int row = m0 + r;
            if (row >= n) row = n - 1;
            cp_async16(&Ad[r * KC + c4 * 4], &A[(size_t)row * K + kc + c4 * 4]);
        }
#pragma unroll
        for (int t = tid; t < BSZ / 4; t += 256) {
            int r  = t / (C / 4);
            int c4 = t % (C / 4);
            cp_async16(&Bd[r * C + c4 * 4], &Wf1[(size_t)(kc + r) * C + c4 * 4]);
        }
        CP_COMMIT();
    };

    float acc[TM][TN];
#pragma unroll
    for (int i = 0; i < TM; i++)
#pragma unroll
        for (int j = 0; j < TN; j++) acc[i][j] = 0.0f;

    load(0, 0);
    for (int ch = 0; ch < NCH; ch++) {
        if (ch + 1 < NCH) { load(ch + 1, (ch + 1) & 1); CP_WAIT(1); }
        else              { CP_WAIT(0); }
        __syncthreads();
        const float* Acur = AshB[ch & 1];
        const float* Bcur = BshB[ch & 1];
#pragma unroll
        for (int k4 = 0; k4 < KC / 4; k4++) {
            float4 b0 = *reinterpret_cast<const float4*>(&Bcur[(k4 * 4 + 0) * C + tc * TN]);
            float4 b1 = *reinterpret_cast<const float4*>(&Bcur[(k4 * 4 + 1) * C + tc * TN]);
            float4 b2 = *reinterpret_cast<const float4*>(&Bcur[(k4 * 4 + 2) * C + tc * TN]);
            float4 b3 = *reinterpret_cast<const float4*>(&Bcur[(k4 * 4 + 3) * C + tc * TN]);
#pragma unroll
            for (int i = 0; i < TM; i++) {
                float4 a = *reinterpret_cast<const float4*>(&Acur[(tr * TM + i) * KC + k4 * 4]);
                acc[i][0] += a.x * b0.x + a.y * b1.x + a.z * b2.x + a.w * b3.x;
                acc[i][1] += a.x * b0.y + a.y * b1.y + a.z * b2.y + a.w * b3.y;
                acc[i][2] += a.x * b0.z + a.y * b1.z + a.z * b2.z + a.w * b3.z;
                acc[i][3] += a.x * b0.w + a.y * b1.w + a.z * b2.w + a.w * b3.w;
            }
        }
        __syncthreads();
    }

    // write tanh(acc + bias) into padded a1 smem (aliases dead A/B buffers)
    float bv0 = bf1[tc * TN + 0], bv1 = bf1[tc * TN + 1];
    float bv2 = bf1[tc * TN + 2], bv3 = bf1[tc * TN + 3];
#pragma unroll
    for (int i = 0; i < TM; i++) {
        int r = tr * TM + i;
        float* dst = &a1sh[r * 65 + tc * TN];
        dst[0] = tanhf(acc[i][0] + bv0);
        dst[1] = tanhf(acc[i][1] + bv1);
        dst[2] = tanhf(acc[i][2] + bv2);
        dst[3] = tanhf(acc[i][3] + bv3);
    }
    __syncthreads();

    // logits: each thread handles 4 (row, d) pairs
#pragma unroll
    for (int q = 0; q < 4; q++) {
        int idx = tid * 4 + q;      // 0..1023
        int r   = idx >> 3;         // 0..127
        int d   = idx & 7;
        int row = m0 + r;
        if (row >= n) continue;
        float s = bf2sh[d];
        const float* ar = &a1sh[r * 65];
#pragma unroll 8
        for (int j = 0; j < 64; j++) s += ar[j] * Wf2sh[j * 8 + d];
        float e = expf(s);
        g_s[(size_t)row * 8 + d] = e;
        atomicAdd(&redZ[d], e);
    }
    __syncthreads();
    if (tid < 8) atomicAdd(&g_Z[tid], redZ[tid]);
}

// ---------------- CSR gather, bf16 payload (R8-proven) -------------------------
__global__ void gather128(const __nv_bfloat16* __restrict__ hs,
                          const float* __restrict__ b1,
                          float* __restrict__ out, int n) {
    int warp = (blockIdx.x * blockDim.x + threadIdx.x) >> 5;
    int lane = threadIdx.x & 31;
    if (warp >= n) return;
    const int node = warp;
    const uint2* base = reinterpret_cast<const uint2*>(hs);
    uint2 ps = __ldg(base + (size_t)node * 32 + lane);
    float4 a0 = make_float4(bf_lo(ps.x), bf_hi(ps.x), bf_lo(ps.y), bf_hi(ps.y));
    float4 a1 = make_float4(0.f, 0.f, 0.f, 0.f);
    int j = g_off[node], jend = g_off[node + 1];
    for (; j + 4 <= jend; j += 4) {
        int s0 = __ldg(&g_ecsr[j]);
        int s1 = __ldg(&g_ecsr[j + 1]);
        int s2 = __ldg(&g_ecsr[j + 2]);
        int s3 = __ldg(&g_ecsr[j + 3]);
        uint2 p0 = __ldg(base + (size_t)s0 * 32 + lane);
        uint2 p1 = __ldg(base + (size_t)s1 * 32 + lane);
        uint2 p2 = __ldg(base + (size_t)s2 * 32 + lane);
        uint2 p3 = __ldg(base + (size_t)s3 * 32 + lane);
        a0.x += bf_lo(p0.x) + bf_lo(p1.x); a0.y += bf_hi(p0.x) + bf_hi(p1.x);
        a0.z += bf_lo(p0.y) + bf_lo(p1.y); a0.w += bf_hi(p0.y) + bf_hi(p1.y);
        a1.x += bf_lo(p2.x) + bf_lo(p3.x); a1.y += bf_hi(p2.x) + bf_hi(p3.x);
        a1.z += bf_lo(p2.y) + bf_lo(p3.y); a1.w += bf_hi(p2.y) + bf_hi(p3.y);
    }
    for (; j < jend; j++) {
        int s0 = __ldg(&g_ecsr[j]);
        uint2 p0 = __ldg(base + (size_t)s0 * 32 + lane);
        a0.x += bf_lo(p0.x); a0.y += bf_hi(p0.x);
        a0.z += bf_lo(p0.y); a0.w += bf_hi(p0.y);
    }
    float4 acc = make_float4(a0.x + a1.x, a0.y + a1.y, a0.z + a1.z, a0.w + a1.w);
    float dn = g_dinv[node];
    float4 bb = *reinterpret_cast<const float4*>(&b1[lane * 4]);
    float4 o = make_float4(fmaxf(acc.x * dn + bb.x, 0.f), fmaxf(acc.y * dn + bb.y, 0.f),
                           fmaxf(acc.z * dn + bb.z, 0.f), fmaxf(acc.w * dn + bb.w, 0.f));
    *reinterpret_cast<float4*>(&out[(size_t)node * 128 + lane * 4]) = o;
}

__global__ void gather64(const __nv_bfloat16* __restrict__ hs,
                         const float* __restrict__ b2,
                         float* __restrict__ out, int n) {
    int warp = (blockIdx.x * blockDim.x + threadIdx.x) >> 5;
    int lane = threadIdx.x & 31;
    if (warp >= n) return;
    const int node = warp;
    const unsigned* base = reinterpret_cast<const unsigned*>(hs);
    unsigned ps = __ldg(base + (size_t)node * 32 + lane);
    float2 a0 = make_float2(bf_lo(ps), bf_hi(ps));
    float2 a1 = make_float2(0.f, 0.f);
    int j = g_off[node], jend = g_off[node + 1];
    for (; j + 4 <= jend; j += 4) {
        int s0 = __ldg(&g_ecsr[j]);
        int s1 = __ldg(&g_ecsr[j + 1]);
        int s2 = __ldg(&g_ecsr[j + 2]);
        int s3 = __ldg(&g_ecsr[j + 3]);
        unsigned p0 = __ldg(base + (size_t)s0 * 32 + lane);
        unsigned p1 = __ldg(base + (size_t)s1 * 32 + lane);
        unsigned p2 = __ldg(base + (size_t)s2 * 32 + lane);
        unsigned p3 = __ldg(base + (size_t)s3 * 32 + lane);
        a0.x += bf_lo(p0) + bf_lo(p1); a0.y += bf_hi(p0) + bf_hi(p1);
        a1.x += bf_lo(p2) + bf_lo(p3); a1.y += bf_hi(p2) + bf_hi(p3);
    }
    for (; j < jend; j++) {
        int s0 = __ldg(&g_ecsr[j]);
        unsigned p0 = __ldg(base + (size_t)s0 * 32 + lane);
        a0.x += bf_lo(p0); a0.y += bf_hi(p0);
    }
    float2 acc = make_float2(a0.x + a1.x, a0.y + a1.y);
    float dn = g_dinv[node];
    float2 bb = *reinterpret_cast<const float2*>(&b2[2 * lane]);
    float2 o = make_float2(acc.x * dn + bb.x, acc.y * dn + bb.y);
    *reinterpret_cast<float2*>(&out[(size_t)node * 64 + 2 * lane]) = o;
}

// ---------------- pooled reductions: G = e.T@h2, C = e.T@e --------------------
__global__ void k_accum(int n) {
    __shared__ float h2sh[64 * 64];
    __shared__ float esh[64 * 8];
    int tid = threadIdx.x;
    int c0  = blockIdx.x * 64;
    int nv  = n - c0;
    if (nv > 64) nv = 64;

    for (int t = tid; t < 64 * 64; t += 256) {
        int row = t >> 6;
        if (row < nv) h2sh[t] = g_h2[(size_t)(c0 + row) * 64 + (t & 63)];
    }
    for (int t = tid; t < 512; t += 256) {
        int row = t >> 3;
        if (row < nv) esh[t] = g_s[(size_t)(c0 + row) * 8 + (t & 7)];
    }
    __syncthreads();

    int p0 = tid, p1 = tid + 256;
    int d0 = p0 >> 6, h0 = p0 & 63;
    int d1 = p1 >> 6, h1 = p1 & 63;
    int cd1 = tid >> 3, cd2 = tid & 7;
    float aG0 = 0.f, aG1 = 0.f, aC = 0.f;
    for (int m = 0; m < nv; m++) {
        float* hrow = &h2sh[m * 64];
        float* erow = &esh[m * 8];
        aG0 += erow[d0] * hrow[h0];
        aG1 += erow[d1] * hrow[h1];
        if (tid < 64) aC += erow[cd1] * erow[cd2];
    }
    atomicAdd(&g_G[p0], aG0);
    atomicAdd(&g_G[p1], aG1);
    if (tid < 64) atomicAdd(&g_C[tid], aC);
}

// ---------------- final: normalize, penalty, dense head, log_softmax ----------
__global__ void k_final(const float* __restrict__ Wl, const float* __restrict__ bl,
                        float* __restrict__ out) {
    __shared__ float ge[512];
    __shared__ float Zs[8];
    __shared__ float tmp[16];
    __shared__ float lg[10];
    int tid = threadIdx.x; // 64 threads
    if (tid < 8) Zs[tid] = g_Z[tid];
    __syncthreads();
    for (int p = tid; p < 512; p += 64) {
        float v = g_G[p] / Zs[p >> 6];
        ge[p]  = v;
        out[p] = v;
    }
    __syncthreads();
    if (tid < 8) {
        float ss = 0.f;
        for (int d2 = 0; d2 < 8; d2++) {
            float c = g_C[tid * 8 + d2] / (Zs[tid] * Zs[d2]) - (tid == d2 ? 1.0f : 0.0f);
            ss += c * c;
        }
        tmp[tid] = sqrtf(ss);
    }
    __syncthreads();
    if (tid == 0) {
        float pen = 0.f;
        for (int d = 0; d < 8; d++) pen += tmp[d];
        out[512] = pen;
    }
    if (tid < 10) {
        float acc = bl[tid];
        for (int p = 0; p < 512; p++) acc += ge[p] * Wl[p * 10 + tid];
        lg[tid] = acc;
    }
    __syncthreads();
    if (tid == 0) {
        float m = lg[0];
        for (int l = 1; l < 10; l++) m = fmaxf(m, lg[l]);
        float s = 0.f;
        for (int l = 0; l < 10; l++) s += expf(lg[l] - m);
        tmp[0] = m + logf(s);
    }
    __syncthreads();
    if (tid < 10) out[513 + tid] = lg[tid] - tmp[0];
}

// ---------------- launch -------------------------------------------------------
extern "C" void kernel_launch(void* const* d_in, const int* in_sizes, int n_in,
                              void* d_out, int out_size) {
    const int*   edges = (const int*)d_in[0];
    const float* X     = (const float*)d_in[1];
    const float* W1    = (const float*)d_in[2];
    const float* b1    = (const float*)d_in[3];
    const float* W2    = (const float*)d_in[4];
    const float* b2    = (const float*)d_in[5];
    const float* Wf1   = (const float*)d_in[6];
    const float* bf1   = (const float*)d_in[7];
    const float* Wf2   = (const float*)d_in[8];
    const float* bf2   = (const float*)d_in[9];
    const float* Wl    = (const float*)d_in[10];
    const float* bl    = (const float*)d_in[11];
    float* out = (float*)d_out;

    int e = in_sizes[0] / 2;
    int n = in_sizes[1] / 128;
    const int* src = edges;
    const int* dst = edges + e;

    __nv_bfloat16 *pHs1, *pH2s;
    float *pH1, *pH2;
    cudaGetSymbolAddress((void**)&pHs1, g_hs1);
    cudaGetSymbolAddress((void**)&pH1,  g_h1);
    cudaGetSymbolAddress((void**)&pH2s, g_h2s);
    cudaGetSymbolAddress((void**)&pH2,  g_h2);

    // dynamic smem: double-buffered A+B chunks
    const int SM1 = 2 * (128 * 32 + 32 * 128) * 4;  // 65536
    const int SM2 = 2 * (128 * 32 + 32 * 64) * 4;   // 49152
    const int SM3 = 2 * (128 * 32 + 32 * 64) * 4;   // 49152
    cudaFuncSetAttribute((const void*)gemm_kernel<128, 128>,
                         cudaFuncAttributeMaxDynamicSharedMemorySize, SM1);
    cudaFuncSetAttribute((const void*)gemm_kernel<128, 64>,
                         cudaFuncAttributeMaxDynamicSharedMemorySize, SM2);
    cudaFuncSetAttribute((const void*)gemm3_logits,
                         cudaFuncAttributeMaxDynamicSharedMemorySize, SM3);

    const int T  = 256;
    const int NB = (n + 1023) / 1024;

    // CSR build + dinv (single stream)
    k_init  <<<(n + T - 1) / T, T>>>(n);
    k_deg   <<<(e + T - 1) / T, T>>>(dst, e);
    k_scan1 <<<NB, 1024>>>(n);
    k_scan3 <<<NB, 1024>>>(n);
    k_bucket<<<(e + T - 1) / T, T>>>(src, dst, e);

    // layer 1: hs1 = (X@W1)*dinv (bf16); h1 = relu(gather(hs1)*dinv + b1)
    gemm_kernel<128, 128><<<(n + 127) / 128, T, SM1>>>(X, W1, pHs1, n);
    gather128<<<(n + 7) / 8, T>>>(pHs1, b1, pH1, n);

    // layer 2: h2s = (h1@W2)*dinv (bf16); h2 = gather(h2s)*dinv + b2
    gemm_kernel<128, 64><<<(n + 127) / 128, T, SM2>>>(pH1, W2, pH2s, n);
    gather64<<<(n + 7) / 8, T>>>(pH2s, b2, pH2, n);

    // attention: gemm3 + logits fused (a1 never leaves smem)
    gemm3_logits<<<(n + 127) / 128, T, SM3>>>(pH2, Wf1, bf1, Wf2, bf2, n);
    k_accum<<<(n + 63) / 64, T>>>(n);

    // head
    k_final<<<1, 64>>>(Wl, bl, out);
}

// round 16
// speedup vs baseline: 1.0615x; 1.0615x over previous
#include <cuda_runtime.h>
#include <cuda_bf16.h>
#include <math.h>

#define MAXN 100000
#define MAXE 3200000

// ---------------- scratch (static device globals; no allocation) -------------
__device__ __nv_bfloat16 g_hs1[(size_t)MAXN * 128]; // (X@W1)*dinv, bf16 payload
__device__ float g_h1 [(size_t)MAXN * 128];         // h1
__device__ __nv_bfloat16 g_h2s[(size_t)MAXN * 64];  // (h1@W2)*dinv, bf16 payload
__device__ float g_h2 [(size_t)MAXN * 64];          // h2
__device__ float g_s  [(size_t)MAXN * 8];           // exp(attention logits)
__device__ float g_dinv[MAXN];
__device__ int   g_cnt [MAXN];
__device__ int   g_tmp [MAXN];
__device__ int   g_off [MAXN + 1];
__device__ int   g_cur [MAXN];
__device__ int   g_ecsr[MAXE];
__device__ int   g_bsum[128];
__device__ int   g_bpre[128];
__device__ float g_Z[8];
__device__ float g_G[512];
__device__ float g_C[64];

// ---------------- bf16 unpack helpers (pure ALU, no cvt pipe) -----------------
__device__ __forceinline__ float bf_lo(unsigned p) { return __uint_as_float(p << 16); }
__device__ __forceinline__ float bf_hi(unsigned p) { return __uint_as_float(p & 0xFFFF0000u); }

// ---------------- init / degree / CSR build ----------------------------------
__global__ void k_init(int n) {
    int i = blockIdx.x * blockDim.x + threadIdx.x;
    if (i < n)   g_cnt[i] = 0;
    if (i < 512) g_G[i] = 0.0f;
    if (i < 64)  g_C[i] = 0.0f;
    if (i < 8)   g_Z[i] = 0.0f;
}

__global__ void k_deg(const int* __restrict__ dst, int e) {
    int i = blockIdx.x * blockDim.x + threadIdx.x;
    if (i < e) atomicAdd(&g_cnt[dst[i]], 1);
}

__global__ void k_dinv(int n) {
    int i = blockIdx.x * blockDim.x + threadIdx.x;
    if (i < n) g_dinv[i] = rsqrtf((float)(g_cnt[i] + 1)); // +1 self loop
}

__global__ void k_scan1(int n) {
    __shared__ int sh[1024];
    int i = blockIdx.x * 1024 + threadIdx.x;
    int v = (i < n) ? g_cnt[i] : 0;
    sh[threadIdx.x] = v;
    __syncthreads();
#pragma unroll
    for (int off = 1; off < 1024; off <<= 1) {
        int t = (threadIdx.x >= off) ? sh[threadIdx.x - off] : 0;
        __syncthreads();
        sh[threadIdx.x] += t;
        __syncthreads();
    }
    if (i < n) g_tmp[i] = sh[threadIdx.x];
    if (threadIdx.x == 1023) g_bsum[blockIdx.x] = sh[1023];
}

__global__ void k_scan2(int nb) { // one block, 128 threads
    int t = threadIdx.x;
    int orig = (t < nb) ? g_bsum[t] : 0;
    int v = orig;
#pragma unroll
    for (int off = 1; off < 32; off <<= 1) {
        int u = __shfl_up_sync(0xFFFFFFFF, v, off);
        if ((t & 31) >= off) v += u;
    }
    __shared__ int ws[4];
    if ((t & 31) == 31) ws[t >> 5] = v;
    __syncthreads();
    int add = 0;
    for (int w = 0; w < (t >> 5); w++) add += ws[w];
    v += add;
    if (t < nb) g_bpre[t] = v - orig; // exclusive
}

__global__ void k_scan3(int n) {
    int i = blockIdx.x * 1024 + threadIdx.x;
    if (i < n) {
        int inc = g_tmp[i] + g_bpre[blockIdx.x];
        g_off[i + 1] = inc;
        g_cur[i]     = inc - g_cnt[i];
    }
    if (i == 0) g_off[0] = 0;
}

__global__ void k_bucket(const int* __restrict__ src, const int* __restrict__ dst, int e) {
    int i = blockIdx.x * blockDim.x + threadIdx.x;
    if (i < e) {
        int d   = dst[i];
        int pos = atomicAdd(&g_cur[d], 1);
        g_ecsr[pos] = src[i];
    }
}

// ---------------- 4x4 register-tiled fp32 GEMM (R2-proven, MODE 0 only) -------
// out_bf16 = (A@W)*dinv[row]
template <int K, int C>
__global__ void gemm_kernel(const float* __restrict__ A,
                            const float* __restrict__ W,
                            __nv_bfloat16* __restrict__ outb,
                            int n) {
    constexpr int BM  = 128;
    constexpr int TN  = 4;
    constexpr int NCG = C / TN;
    constexpr int NRG = 256 / NCG;
    constexpr int TM  = BM / NRG;
    constexpr int KC  = 32;

    __shared__ float Ash[BM * KC];
    __shared__ float Bsh[KC * C];

    int tid = threadIdx.x;
    int m0  = blockIdx.x * BM;
    int tc  = tid % NCG;
    int tr  = tid / NCG;

    float acc[TM][TN];
#pragma unroll
    for (int i = 0; i < TM; i++)
#pragma unroll
        for (int j = 0; j < TN; j++) acc[i][j] = 0.0f;

    for (int kc = 0; kc < K; kc += KC) {
        constexpr int AF4 = BM * KC / 4;
#pragma unroll
        for (int t = tid; t < AF4; t += 256) {
            int r  = t / (KC / 4);
            int c4 = t % (KC / 4);
            float4 v = make_float4(0.f, 0.f, 0.f, 0.f);
            int row = m0 + r;
            if (row < n)
                v = *reinterpret_cast<const float4*>(&A[(size_t)row * K + kc + c4 * 4]);
            *reinterpret_cast<float4*>(&Ash[r * KC + c4 * 4]) = v;
        }
        constexpr int BF4 = KC * C / 4;
#pragma unroll
        for (int t = tid; t < BF4; t += 256) {
            int r  = t / (C / 4);
            int c4 = t % (C / 4);
            *reinterpret_cast<float4*>(&Bsh[r * C + c4 * 4]) =
                *reinterpret_cast<const float4*>(&W[(size_t)(kc + r) * C + c4 * 4]);
        }
        __syncthreads();
#pragma unroll
        for (int k4 = 0; k4 < KC / 4; k4++) {
            float4 b0 = *reinterpret_cast<const float4*>(&Bsh[(k4 * 4 + 0) * C + tc * TN]);
            float4 b1 = *reinterpret_cast<const float4*>(&Bsh[(k4 * 4 + 1) * C + tc * TN]);
            float4 b2 = *reinterpret_cast<const float4*>(&Bsh[(k4 * 4 + 2) * C + tc * TN]);
            float4 b3 = *reinterpret_cast<const float4*>(&Bsh[(k4 * 4 + 3) * C + tc * TN]);
#pragma unroll
            for (int i = 0; i < TM; i++) {
                float4 a = *reinterpret_cast<const float4*>(&Ash[(tr * TM + i) * KC + k4 * 4]);
                acc[i][0] += a.x * b0.x + a.y * b1.x + a.z * b2.x + a.w * b3.x;
                acc[i][1] += a.x * b0.y + a.y * b1.y + a.z * b2.y + a.w * b3.y;
                acc[i][2] += a.x * b0.z + a.y * b1.z + a.z * b2.z + a.w * b3.z;
                acc[i][3] += a.x * b0.w + a.y * b1.w + a.z * b2.w + a.w * b3.w;
            }
        }
        __syncthreads();
    }

#pragma unroll
    for (int i = 0; i < TM; i++) {
        int row = m0 + tr * TM + i;
        if (row >= n) continue;
        float sc = g_dinv[row];
        __nv_bfloat162 lo = __floats2bfloat162_rn(acc[i][0] * sc, acc[i][1] * sc);
        __nv_bfloat162 hi = __floats2bfloat162_rn(acc[i][2] * sc, acc[i][3] * sc);
        uint2 pk = make_uint2(*reinterpret_cast<unsigned*>(&lo),
                              *reinterpret_cast<unsigned*>(&hi));
        *reinterpret_cast<uint2*>(&outb[(size_t)row * C + tc * TN]) = pk;
    }
}

// ---------------- gemm3 fused with attention logits ---------------------------
// a1 = tanh(h2@Wf1 + bf1) (kept in smem); s = a1@Wf2 + bf2; g_s = exp(s);
// Z partials block-reduced, 8 global atomics per block.
__global__ void __launch_bounds__(256)
gemm3_logits(const float* __restrict__ A,      // h2 [n,64]
             const float* __restrict__ Wf1,    // [64,64]
             const float* __restrict__ bf1,    // [64]
             const float* __restrict__ Wf2,    // [64,8]
             const float* __restrict__ bf2,    // [8]
             int n) {
    constexpr int K = 64, C = 64;
    constexpr int BM = 128, TN = 4;
    constexpr int NCG = C / TN;   // 16
    constexpr int TM  = 8;
    constexpr int KC  = 32;

    __shared__ union {
        struct { float Ash[BM * KC]; float Bsh[KC * C]; } ld; // 24KB
        float a1sh[BM * 65];                                  // 33.3KB
    } u;
    __shared__ float Wf2sh[64 * 8];
    __shared__ float bf2sh[8];
    __shared__ float redZ[8];

    int tid = threadIdx.x;
    int m0  = blockIdx.x * BM;
    int tc  = tid % NCG;
    int tr  = tid / NCG;

    for (int t = tid; t < 512; t += 256) Wf2sh[t] = Wf2[t];
    if (tid < 8) { bf2sh[tid] = bf2[tid]; redZ[tid] = 0.0f; }

    float acc[TM][TN];
#pragma unroll
    for (int i = 0; i < TM; i++)
#pragma unroll
        for (int j = 0; j < TN; j++) acc[i][j] = 0.0f;

    for (int kc = 0; kc < K; kc += KC) {
        constexpr int AF4 = BM * KC / 4;
#pragma unroll
        for (int t = tid; t < AF4; t += 256) {
            int r  = t / (KC / 4);
            int c4 = t % (KC / 4);
            float4 v = make_float4(0.f, 0.f, 0.f, 0.f);
            int row = m0 + r;
            if (row < n)
                v = *reinterpret_cast<const float4*>(&A[(size_t)row * K + kc + c4 * 4]);
            *reinterpret_cast<float4*>(&u.ld.Ash[r * KC + c4 * 4]) = v;
        }
        constexpr int BF4 = KC * C / 4;
#pragma unroll
        for (int t = tid; t < BF4; t += 256) {
            int r  = t / (C / 4);
            int c4 = t % (C / 4);
            *reinterpret_cast<float4*>(&u.ld.Bsh[r * C + c4 * 4]) =
                *reinterpret_cast<const float4*>(&Wf1[(size_t)(kc + r) * C + c4 * 4]);
        }
        __syncthreads();
#pragma unroll
        for (int k4 = 0; k4 < KC / 4; k4++) {
            float4 b0 = *reinterpret_cast<const float4*>(&u.ld.Bsh[(k4 * 4 + 0) * C + tc * TN]);
            float4 b1 = *reinterpret_cast<const float4*>(&u.ld.Bsh[(k4 * 4 + 1) * C + tc * TN]);
            float4 b2 = *reinterpret_cast<const float4*>(&u.ld.Bsh[(k4 * 4 + 2) * C + tc * TN]);
            float4 b3 = *reinterpret_cast<const float4*>(&u.ld.Bsh[(k4 * 4 + 3) * C + tc * TN]);
#pragma unroll
            for (int i = 0; i < TM; i++) {
                float4 a = *reinterpret_cast<const float4*>(&u.ld.Ash[(tr * TM + i) * KC + k4 * 4]);
                acc[i][0] += a.x * b0.x + a.y * b1.x + a.z * b2.x + a.w * b3.x;
                acc[i][1] += a.x * b0.y + a.y * b1.y + a.z * b2.y + a.w * b3.y;
                acc[i][2] += a.x * b0.z + a.y * b1.z + a.z * b2.z + a.w * b3.z;
                acc[i][3] += a.x * b0.w + a.y * b1.w + a.z * b2.w + a.w * b3.w;
            }
        }
        __syncthreads();
    }

    float bv0 = bf1[tc * TN + 0], bv1 = bf1[tc * TN + 1];
    float bv2 = bf1[tc * TN + 2], bv3 = bf1[tc * TN + 3];
#pragma unroll
    for (int i = 0; i < TM; i++) {
        int r = tr * TM + i;
        float* dst = &u.a1sh[r * 65 + tc * TN];
        dst[0] = tanhf(acc[i][0] + bv0);
        dst[1] = tanhf(acc[i][1] + bv1);
        dst[2] = tanhf(acc[i][2] + bv2);
        dst[3] = tanhf(acc[i][3] + bv3);
    }
    __syncthreads();

#pragma unroll
    for (int q = 0; q < 4; q++) {
        int idx = tid * 4 + q;
        int r   = idx >> 3;
        int d   = idx & 7;
        int row = m0 + r;
        if (row >= n) continue;
        float s = bf2sh[d];
        const float* ar = &u.a1sh[r * 65];
#pragma unroll 8
        for (int j = 0; j < 64; j++) s += ar[j] * Wf2sh[j * 8 + d];
        float e = expf(s);
        g_s[(size_t)row * 8 + d] = e;
        atomicAdd(&redZ[d], e);
    }
    __syncthreads();
    if (tid < 8) atomicAdd(&g_Z[tid], redZ[tid]);
}

// ---------------- CSR gather, bf16 payload (R8-proven) -------------------------
__global__ void gather128(const __nv_bfloat16* __restrict__ hs,
                          const float* __restrict__ b1,
                          float* __restrict__ out, int n) {
    int warp = (blockIdx.x * blockDim.x + threadIdx.x) >> 5;
    int lane = threadIdx.x & 31;
    if (warp >= n) return;
    const int node = warp;
    const uint2* base = reinterpret_cast<const uint2*>(hs);
    uint2 ps = __ldg(base + (size_t)node * 32 + lane);
    float4 a0 = make_float4(bf_lo(ps.x), bf_hi(ps.x), bf_lo(ps.y), bf_hi(ps.y));
    float4 a1 = make_float4(0.f, 0.f, 0.f, 0.f);
    int j = g_off[node], jend = g_off[node + 1];
    for (; j + 4 <= jend; j += 4) {
        int s0 = __ldg(&g_ecsr[j]);
        int s1 = __ldg(&g_ecsr[j + 1]);
        int s2 = __ldg(&g_ecsr[j + 2]);
        int s3 = __ldg(&g_ecsr[j + 3]);
        uint2 p0 = __ldg(base + (size_t)s0 * 32 + lane);
        uint2 p1 = __ldg(base + (size_t)s1 * 32 + lane);
        uint2 p2 = __ldg(base + (size_t)s2 * 32 + lane);
        uint2 p3 = __ldg(base + (size_t)s3 * 32 + lane);
        a0.x += bf_lo(p0.x) + bf_lo(p1.x); a0.y += bf_hi(p0.x) + bf_hi(p1.x);
        a0.z += bf_lo(p0.y) + bf_lo(p1.y); a0.w += bf_hi(p0.y) + bf_hi(p1.y);
        a1.x += bf_lo(p2.x) + bf_lo(p3.x); a1.y += bf_hi(p2.x) + bf_hi(p3.x);
        a1.z += bf_lo(p2.y) + bf_lo(p3.y); a1.w += bf_hi(p2.y) + bf_hi(p3.y);
    }
    for (; j < jend; j++) {
        int s0 = __ldg(&g_ecsr[j]);
        uint2 p0 = __ldg(base + (size_t)s0 * 32 + lane);
        a0.x += bf_lo(p0.x); a0.y += bf_hi(p0.x);
        a0.z += bf_lo(p0.y); a0.w += bf_hi(p0.y);
    }
    float4 acc = make_float4(a0.x + a1.x, a0.y + a1.y, a0.z + a1.z, a0.w + a1.w);
    float dn = g_dinv[node];
    float4 bb = *reinterpret_cast<const float4*>(&b1[lane * 4]);
    float4 o = make_float4(fmaxf(acc.x * dn + bb.x, 0.f), fmaxf(acc.y * dn + bb.y, 0.f),
                           fmaxf(acc.z * dn + bb.z, 0.f), fmaxf(acc.w * dn + bb.w, 0.f));
    *reinterpret_cast<float4*>(&out[(size_t)node * 128 + lane * 4]) = o;
}

__global__ void gather64(const __nv_bfloat16* __restrict__ hs,
                         const float* __restrict__ b2,
                         float* __restrict__ out, int n) {
    int warp = (blockIdx.x * blockDim.x + threadIdx.x) >> 5;
    int lane = threadIdx.x & 31;
    if (warp >= n) return;
    const int node = warp;
    const unsigned* base = reinterpret_cast<const unsigned*>(hs);
    unsigned ps = __ldg(base + (size_t)node * 32 + lane);
    float2 a0 = make_float2(bf_lo(ps), bf_hi(ps));
    float2 a1 = make_float2(0.f, 0.f);
    int j = g_off[node], jend = g_off[node + 1];
    for (; j + 4 <= jend; j += 4) {
        int s0 = __ldg(&g_ecsr[j]);
        int s1 = __ldg(&g_ecsr[j + 1]);
        int s2 = __ldg(&g_ecsr[j + 2]);
        int s3 = __ldg(&g_ecsr[j + 3]);
        unsigned p0 = __ldg(base + (size_t)s0 * 32 + lane);
        unsigned p1 = __ldg(base + (size_t)s1 * 32 + lane);
        unsigned p2 = __ldg(base + (size_t)s2 * 32 + lane);
        unsigned p3 = __ldg(base + (size_t)s3 * 32 + lane);
        a0.x += bf_lo(p0) + bf_lo(p1); a0.y += bf_hi(p0) + bf_hi(p1);
        a1.x += bf_lo(p2) + bf_lo(p3); a1.y += bf_hi(p2) + bf_hi(p3);
    }
    for (; j < jend; j++) {
        int s0 = __ldg(&g_ecsr[j]);
        unsigned p0 = __ldg(base + (size_t)s0 * 32 + lane);
        a0.x += bf_lo(p0); a0.y += bf_hi(p0);
    }
    float2 acc = make_float2(a0.x + a1.x, a0.y + a1.y);
    float dn = g_dinv[node];
    float2 bb = *reinterpret_cast<const float2*>(&b2[2 * lane]);
    float2 o = make_float2(acc.x * dn + bb.x, acc.y * dn + bb.y);
    *reinterpret_cast<float2*>(&out[(size_t)node * 64 + 2 * lane]) = o;
}

// ---------------- pooled reductions: G = e.T@h2, C = e.T@e --------------------
__global__ void k_accum(int n) {
    __shared__ float h2sh[64 * 64];
    __shared__ float esh[64 * 8];
    int tid = threadIdx.x;
    int c0  = blockIdx.x * 64;
    int nv  = n - c0;
    if (nv > 64) nv = 64;

    for (int t = tid; t < 64 * 64; t += 256) {
        int row = t >> 6;
        if (row < nv) h2sh[t] = g_h2[(size_t)(c0 + row) * 64 + (t & 63)];
    }
    for (int t = tid; t < 512; t += 256) {
        int row = t >> 3;
        if (row < nv) esh[t] = g_s[(size_t)(c0 + row) * 8 + (t & 7)];
    }
    __syncthreads();

    int p0 = tid, p1 = tid + 256;
    int d0 = p0 >> 6, h0 = p0 & 63;
    int d1 = p1 >> 6, h1 = p1 & 63;
    int cd1 = tid >> 3, cd2 = tid & 7;
    float aG0 = 0.f, aG1 = 0.f, aC = 0.f;
    for (int m = 0; m < nv; m++) {
        float* hrow = &h2sh[m * 64];
        float* erow = &esh[m * 8];
        aG0 += erow[d0] * hrow[h0];
        aG1 += erow[d1] * hrow[h1];
        if (tid < 64) aC += erow[cd1] * erow[cd2];
    }
    atomicAdd(&g_G[p0], aG0);
    atomicAdd(&g_G[p1], aG1);
    if (tid < 64) atomicAdd(&g_C[tid], aC);
}

// ---------------- final: normalize, penalty, dense head, log_softmax ----------
__global__ void k_final(const float* __restrict__ Wl, const float* __restrict__ bl,
                        float* __restrict__ out) {
    __shared__ float ge[512];
    __shared__ float Zs[8];
    __shared__ float tmp[16];
    __shared__ float lg[10];
    int tid = threadIdx.x; // 64 threads
    if (tid < 8) Zs[tid] = g_Z[tid];
    __syncthreads();
    for (int p = tid; p < 512; p += 64) {
        float v = g_G[p] / Zs[p >> 6];
        ge[p]  = v;
        out[p] = v;
    }
    __syncthreads();
    if (tid < 8) {
        float ss = 0.f;
        for (int d2 = 0; d2 < 8; d2++) {
            float c = g_C[tid * 8 + d2] / (Zs[tid] * Zs[d2]) - (tid == d2 ? 1.0f : 0.0f);
            ss += c * c;
        }
        tmp[tid] = sqrtf(ss);
    }
    __syncthreads();
    if (tid == 0) {
        float pen = 0.f;
        for (int d = 0; d < 8; d++) pen += tmp[d];
        out[512] = pen;
    }
    if (tid < 10) {
        float acc = bl[tid];
        for (int p = 0; p < 512; p++) acc += ge[p] * Wl[p * 10 + tid];
        lg[tid] = acc;
    }
    __syncthreads();
    if (tid == 0) {
        float m = lg[0];
        for (int l = 1; l < 10; l++) m = fmaxf(m, lg[l]);
        float s = 0.f;
        for (int l = 0; l < 10; l++) s += expf(lg[l] - m);
        tmp[0] = m + logf(s);
    }
    __syncthreads();
    if (tid < 10) out[513 + tid] = lg[tid] - tmp[0];
}

// ---------------- launch -------------------------------------------------------
extern "C" void kernel_launch(void* const* d_in, const int* in_sizes, int n_in,
                              void* d_out, int out_size) {
    const int*   edges = (const int*)d_in[0];
    const float* X     = (const float*)d_in[1];
    const float* W1    = (const float*)d_in[2];
    const float* b1    = (const float*)d_in[3];
    const float* W2    = (const float*)d_in[4];
    const float* b2    = (const float*)d_in[5];
    const float* Wf1   = (const float*)d_in[6];
    const float* bf1   = (const float*)d_in[7];
    const float* Wf2   = (const float*)d_in[8];
    const float* bf2   = (const float*)d_in[9];
    const float* Wl    = (const float*)d_in[10];
    const float* bl    = (const float*)d_in[11];
    float* out = (float*)d_out;

    int e = in_sizes[0] / 2;
    int n = in_sizes[1] / 128;
    const int* src = edges;
    const int* dst = edges + e;

    __nv_bfloat16 *pHs1, *pH2s;
    float *pH1, *pH2;
    cudaGetSymbolAddress((void**)&pHs1, g_hs1);
    cudaGetSymbolAddress((void**)&pH1,  g_h1);
    cudaGetSymbolAddress((void**)&pH2s, g_h2s);
    cudaGetSymbolAddress((void**)&pH2,  g_h2);

    static cudaStream_t sCsr = nullptr;
    static cudaEvent_t evDeg = nullptr, evCsr = nullptr;
    if (!sCsr) {
        cudaStreamCreateWithFlags(&sCsr, cudaStreamNonBlocking);
        cudaEventCreateWithFlags(&evDeg, cudaEventDisableTiming);
        cudaEventCreateWithFlags(&evCsr, cudaEventDisableTiming);
    }

    const int T  = 256;
    const int NB = (n + 1023) / 1024;

    // main: init + degree + dinv (gemm1 epilogue needs dinv)
    k_init<<<(n + T - 1) / T, T>>>(n);
    k_deg <<<(e + T - 1) / T, T>>>(dst, e);
    k_dinv<<<(n + T - 1) / T, T>>>(n);
    cudaEventRecord(evDeg, 0);

    // side stream: CSR scan + bucket (overlaps gemm1)
    cudaStreamWaitEvent(sCsr, evDeg, 0);
    k_scan1 <<<NB, 1024, 0, sCsr>>>(n);
    k_scan2 <<<1, 128, 0, sCsr>>>(NB);
    k_scan3 <<<NB, 1024, 0, sCsr>>>(n);
    k_bucket<<<(e + T - 1) / T, T, 0, sCsr>>>(src, dst, e);
    cudaEventRecord(evCsr, sCsr);

    // main: gemm1 concurrent with CSR build
    gemm_kernel<128, 128><<<(n + 127) / 128, T>>>(X, W1, pHs1, n);

    // join, then dependent chain
    cudaStreamWaitEvent(0, evCsr, 0);
    gather128<<<(n + 7) / 8, T>>>(pHs1, b1, pH1, n);
    gemm_kernel<128, 64><<<(n + 127) / 128, T>>>(pH1, W2, pH2s, n);
    gather64<<<(n + 7) / 8, T>>>(pH2s, b2, pH2, n);
    gemm3_logits<<<(n + 127) / 128, T>>>(pH2, Wf1, bf1, Wf2, bf2, n);
    k_accum<<<(n + 63) / 64, T>>>(n);
    k_final<<<1, 64>>>(Wl, bl, out);
}